// round 14
// baseline (speedup 1.0000x reference)
#include <cuda_runtime.h>
#include <cuda.h>
#include <cstdint>
#include <cstddef>

// Problem dims
#define MDIM 8192
#define NDIM 4096
#define KDIM 4096
#define BLK  32

// GEMM tiling (R8 pipeline, R10 warp geometry with slim body)
#define TM 128
#define TN 256
#define KT 32                 // fp32 elements per K-chunk = one K-block = 128B row
#define NSTAGES 4
#define NKITER (KDIM / KT)    // 128
#define NWC 16                // compute warps (4m x 4n, warp tile 32x64)
#define THREADS 544           // 16 compute warps + 1 producer warp

#define A_BYTES (TM * KT * 4)         // 16384
#define B_BYTES (TN * KT * 4)         // 32768
#define BBLK_BYTES (32 * KT * 4)      // 4096 per n-block
#define STAGE_BYTES (A_BYTES + B_BYTES)               // 49152
#define SMEM_DATA0 1024
#define SMEM_TOTAL (SMEM_DATA0 + NSTAGES * STAGE_BYTES)  // 197632

#define OFF_FULL(s)  (16 + (s) * 8)
#define OFF_EMPTY(s) (64 + (s) * 8)
#define OFF_LIVE     512              // 128 bytes: live mask per k-block

// Scratch (static device globals: allowed, no runtime alloc)
__device__ float g_wm[(size_t)NDIM * (size_t)KDIM];   // masked+tf32+permuted W
__device__ float g_xt[(size_t)MDIM * (size_t)KDIM];   // tf32+permuted x
__device__ unsigned char g_live[(NDIM / TN) * NKITER];  // [16][128]

// ---------------- device helpers ----------------

__device__ __forceinline__ uint32_t smem_u32(const void* p) {
  uint32_t r;
  asm("{ .reg .u64 t; cvta.to.shared.u64 t, %1; cvt.u32.u64 %0, t; }"
      : "=r"(r) : "l"(p));
  return r;
}
__device__ __forceinline__ void mbar_init(uint32_t a, uint32_t cnt) {
  asm volatile("mbarrier.init.shared::cta.b64 [%0], %1;"
               :: "r"(a), "r"(cnt) : "memory");
}
__device__ __forceinline__ void mbar_expect_tx(uint32_t a, uint32_t bytes) {
  asm volatile("mbarrier.arrive.expect_tx.shared::cta.b64 _, [%0], %1;"
               :: "r"(a), "r"(bytes) : "memory");
}
__device__ __forceinline__ void mbar_arrive(uint32_t a) {
  asm volatile("mbarrier.arrive.shared::cta.b64 _, [%0];"
               :: "r"(a) : "memory");
}
__device__ __forceinline__ void mbar_wait(uint32_t a, uint32_t parity) {
  asm volatile(
      "{\n\t.reg .pred P;\n\t"
      "WL%=:\n\t"
      "mbarrier.try_wait.parity.acquire.cta.shared::cta.b64 P, [%0], %1, 0x989680;\n\t"
      "@P bra WD%=;\n\t"
      "bra WL%=;\n\t"
      "WD%=:\n\t}"
      :: "r"(a), "r"(parity) : "memory");
}
__device__ __forceinline__ void tma_load_2d(uint32_t smem_dst, const void* map,
                                            int cx, int cy, uint32_t bar) {
  asm volatile(
      "cp.async.bulk.tensor.2d.shared::cta.global.tile.mbarrier::complete_tx::bytes "
      "[%0], [%1, {%2, %3}], [%4];"
      :: "r"(smem_dst), "l"(map), "r"(cx), "r"(cy), "r"(bar) : "memory");
}
__device__ __forceinline__ uint32_t f2tf32(float f) {
  uint32_t u;
  asm("cvt.rna.tf32.f32 %0, %1;" : "=r"(u) : "f"(f));
  return u;
}
__device__ __forceinline__ void lds64(uint32_t addr, uint32_t& x, uint32_t& y) {
  asm volatile("ld.shared.v2.u32 {%0, %1}, [%2];"
               : "=r"(x), "=r"(y) : "r"(addr));
}
__device__ __forceinline__ void mma_tf32(float* c, uint32_t a0, uint32_t a1,
                                         uint32_t a2, uint32_t a3,
                                         uint32_t b0, uint32_t b1) {
  asm volatile(
      "mma.sync.aligned.m16n8k8.row.col.f32.tf32.tf32.f32 "
      "{%0,%1,%2,%3}, {%4,%5,%6,%7}, {%8,%9}, {%0,%1,%2,%3};"
      : "+f"(c[0]), "+f"(c[1]), "+f"(c[2]), "+f"(c[3])
      : "r"(a0), "r"(a1), "r"(a2), "r"(a3), "r"(b0), "r"(b1));
}

// ---------------- column permutation (R4-verified, unchanged) ----------------
// off = (c4&1)*8 + ks*16 + (c4>>1)*64 + h*4 within each 128B k-block row.
// Conflict-free LDS.64 under the SW128 XOR (grp<<4).

__device__ __forceinline__ int perm_src_col(int p) {
  int h  = p & 1;
  int c4 = ((p >> 1) & 1) | (((p >> 4) & 1) << 1);
  int ks = (p >> 2) & 3;
  return ks * 8 + c4 + 4 * h;
}

// ---------------- pre-pass kernels ----------------

__global__ void __launch_bounds__(256)
premask_kernel(const float4* __restrict__ w, const int* __restrict__ bm,
               float* __restrict__ wm) {
  int t = blockIdx.x * 256 + threadIdx.x;     // [NDIM][KDIM/32]
  int o  = t >> 7;
  int kb = t & 127;
  if (bm[((o >> 5) << 7) + kb] == 0) return;  // dead blocks never TMA-loaded
  const float4* src = w + (size_t)t * 8;
  uint4* dst = reinterpret_cast<uint4*>(wm) + (size_t)t * 8;
  float v[32];
  #pragma unroll
  for (int q = 0; q < 8; q++) {
    float4 f = src[q];
    v[q * 4 + 0] = f.x; v[q * 4 + 1] = f.y; v[q * 4 + 2] = f.z; v[q * 4 + 3] = f.w;
  }
  uint32_t ov[32];
  #pragma unroll
  for (int p = 0; p < 32; p++) ov[p] = f2tf32(v[perm_src_col(p)]);
  #pragma unroll
  for (int q = 0; q < 8; q++)
    dst[q] = make_uint4(ov[q * 4], ov[q * 4 + 1], ov[q * 4 + 2], ov[q * 4 + 3]);
}

__global__ void __launch_bounds__(256)
cvtx_kernel(const float4* __restrict__ x, float* __restrict__ xt) {
  int t = blockIdx.x * 256 + threadIdx.x;
  const float4* src = x + (size_t)t * 8;
  uint4* dst = reinterpret_cast<uint4*>(xt) + (size_t)t * 8;
  float v[32];
  #pragma unroll
  for (int q = 0; q < 8; q++) {
    float4 f = src[q];
    v[q * 4 + 0] = f.x; v[q * 4 + 1] = f.y; v[q * 4 + 2] = f.z; v[q * 4 + 3] = f.w;
  }
  uint32_t ov[32];
  #pragma unroll
  for (int p = 0; p < 32; p++) ov[p] = f2tf32(v[perm_src_col(p)]);
  #pragma unroll
  for (int q = 0; q < 8; q++)
    dst[q] = make_uint4(ov[q * 4], ov[q * 4 + 1], ov[q * 4 + 2], ov[q * 4 + 3]);
}

__global__ void __launch_bounds__(256)
livemask_kernel(const int* __restrict__ bm, unsigned char* __restrict__ lv) {
  int t = blockIdx.x * 256 + threadIdx.x;   // 0..2047
  int cn = t >> 7, kb = t & 127;
  unsigned b = 0;
  #pragma unroll
  for (int j = 0; j < 8; j++)
    b |= (bm[(cn * 8 + j) * 128 + kb] ? 1u : 0u) << j;
  lv[t] = (unsigned char)b;
}

// ---------------- GEMM ----------------
// CTA 128x256, 16 compute warps + 1 producer. Warp geometry: 4m x 4n, warp
// tile 32x64 covering n-block pair {jA=w>>2, jB=jA+4} at quarter height
// (mrow = w&3 = SMSP). Every SMSP hosts one warp of EVERY n-block, so the
// per-round SMSP MMA load is popc(live)*32 on all four SMSPs — deterministic
// balance (gate = mean, vs R8's E[max Bin(4,1/2)] = 2.56 units).
// Unlike failed R10: body kept R8-sized — shared A fragments loaded once per
// ks-pair, then two slim if(live-half) blocks (4 B-LDS + 8 MMA per ks), no
// template blowup. Pipeline/k-order/parity identical to R8.

__global__ void __launch_bounds__(THREADS, 1)
bsl_gemm_kernel(const __grid_constant__ CUtensorMap tmA,
                const __grid_constant__ CUtensorMap tmB,
                const float* __restrict__ bias,
                float* __restrict__ out) {
  extern __shared__ char smem[];
  const uint32_t sb = smem_u32(smem);
  const int tid  = threadIdx.x;
  const int w    = tid >> 5;
  const int lane = tid & 31;
  const int grp  = lane >> 2;
  const int c4   = lane & 3;

  // grid: x = n-tile (16), y = m-tile (64)  -> wave-blocked for L2 reuse
  const int n0 = blockIdx.x * TN;
  const int m0 = blockIdx.y * TM;

  if (tid == 0) {
    #pragma unroll
    for (int s = 0; s < NSTAGES; s++) {
      mbar_init(sb + OFF_FULL(s), 1);
      mbar_init(sb + OFF_EMPTY(s), NWC);
    }
    asm volatile("fence.proxy.async.shared::cta;" ::: "memory");
  }
  if (tid < 32) {
    reinterpret_cast<uint32_t*>(smem + OFF_LIVE)[tid] =
        reinterpret_cast<const uint32_t*>(g_live)[blockIdx.x * 32 + tid];
  }
  __syncthreads();

  const unsigned char* lv = reinterpret_cast<const unsigned char*>(smem + OFF_LIVE);

  if (w == NWC) {
    // -------- producer warp (identical to R8) --------
    if (lane == 0) {
      for (int kb = 0; kb < NKITER; kb++) {
        const int st = kb & (NSTAGES - 1);
        if (kb >= NSTAGES) mbar_wait(sb + OFF_EMPTY(st), ((kb - NSTAGES) >> 2) & 1);
        const unsigned L = lv[kb];
        const uint32_t tx = (L ? A_BYTES : 0u) + (uint32_t)__popc(L) * BBLK_BYTES;
        mbar_expect_tx(sb + OFF_FULL(st), tx);
        const uint32_t dst = sb + SMEM_DATA0 + st * STAGE_BYTES;
        if (L) tma_load_2d(dst, &tmA, kb * KT, m0, sb + OFF_FULL(st));
        #pragma unroll
        for (int j = 0; j < 8; j++)
          if ((L >> j) & 1)
            tma_load_2d(dst + A_BYTES + j * BBLK_BYTES, &tmB, kb * KT,
                        n0 + j * 32, sb + OFF_FULL(st));
      }
    }
    return;
  }

  // -------- compute warps: mrow = w&3 (= SMSP), ncol pair {w>>2, (w>>2)+4} --
  const int mrow = w & 3;            // m offset 32*mrow
  const int jA   = w >> 2;           // first n-block (0..3)
  const int jB   = jA + 4;           // second n-block (4..7)
  const int wm_  = mrow * 32;

  const uint32_t arow0 = (uint32_t)((wm_ + grp) * 128);
  const uint32_t browA = (uint32_t)(jA * BBLK_BYTES + grp * 128);
  const uint32_t browB = (uint32_t)(jB * BBLK_BYTES + grp * 128);
  const uint32_t xorb =
      (((uint32_t)(c4 & 1) << 3) | ((uint32_t)(c4 >> 1) << 6)) ^
      ((uint32_t)grp << 4);
  uint32_t cxs[4];
  #pragma unroll
  for (int ks = 0; ks < 4; ks++) cxs[ks] = ((uint32_t)(ks << 4)) ^ xorb;

  float acc[2][8][4];
  #pragma unroll
  for (int mt = 0; mt < 2; mt++)
    #pragma unroll
    for (int nt = 0; nt < 8; nt++)
      #pragma unroll
      for (int r = 0; r < 4; r++) acc[mt][nt][r] = 0.f;

  for (int kb = 0; kb < NKITER; kb++) {
    const int st = kb & (NSTAGES - 1);
    mbar_wait(sb + OFF_FULL(st), (kb >> 2) & 1);
    const unsigned L = lv[kb];
    const bool l0 = (L >> jA) & 1;
    const bool l1 = (L >> jB) & 1;
    if (l0 | l1) {
      const uint32_t base = sb + SMEM_DATA0 + st * STAGE_BYTES;
      const uint32_t Ab  = base + arow0;
      const uint32_t Bb0 = base + A_BYTES + browA;
      const uint32_t Bb1 = base + A_BYTES + browB;
      // Two ks per pass: A fragments shared across both halves.
      #pragma unroll
      for (int p = 0; p < 2; p++) {
        uint32_t a[2][8];
        #pragma unroll
        for (int q = 0; q < 2; q++) {
          const uint32_t cx = cxs[2 * p + q];
          #pragma unroll
          for (int mt = 0; mt < 2; mt++) {
            lds64(Ab + mt * 2048 + cx,        a[q][mt * 4 + 0], a[q][mt * 4 + 2]);
            lds64(Ab + mt * 2048 + 1024 + cx, a[q][mt * 4 + 1], a[q][mt * 4 + 3]);
          }
        }
        #pragma unroll
        for (int h = 0; h < 2; h++) {
          if (h ? l1 : l0) {
            const uint32_t Bb = h ? Bb1 : Bb0;
            #pragma unroll
            for (int q = 0; q < 2; q++) {
              const uint32_t cx = cxs[2 * p + q];
              uint32_t b[8];
              #pragma unroll
              for (int nt = 0; nt < 4; nt++)
                lds64(Bb + nt * 1024 + cx, b[nt * 2], b[nt * 2 + 1]);
              #pragma unroll
              for (int mt = 0; mt < 2; mt++)
                #pragma unroll
                for (int nt = 0; nt < 4; nt++)
                  mma_tf32(acc[mt][h * 4 + nt],
                           a[q][mt * 4 + 0], a[q][mt * 4 + 1],
                           a[q][mt * 4 + 2], a[q][mt * 4 + 3],
                           b[nt * 2], b[nt * 2 + 1]);
            }
          }
        }
      }
    }
    if (lane == 0) mbar_arrive(sb + OFF_EMPTY(st));
  }

  // -------- epilogue: rows wm_+mt*16+{grp,grp+8}, cols blocks jA and jB --
  #pragma unroll
  for (int h = 0; h < 2; h++) {
    const int jj = h ? jB : jA;
    #pragma unroll
    for (int nt = 0; nt < 4; nt++) {
      const int col = n0 + jj * 32 + nt * 8 + c4 * 2;
      const float2 bv = *reinterpret_cast<const float2*>(bias + col);
      #pragma unroll
      for (int mt = 0; mt < 2; mt++) {
        const float* ac = acc[mt][h * 4 + nt];
        const int row = m0 + wm_ + mt * 16 + grp;
        float2 o0, o1;
        o0.x = ac[0] + bv.x;
        o0.y = ac[1] + bv.y;
        o1.x = ac[2] + bv.x;
        o1.y = ac[3] + bv.y;
        *reinterpret_cast<float2*>(out + (size_t)row * NDIM + col) = o0;
        *reinterpret_cast<float2*>(out + (size_t)(row + 8) * NDIM + col) = o1;
      }
    }
  }
}

// ---------------- host launch ----------------

typedef CUresult (*EncodeTiledFn)(
    CUtensorMap*, CUtensorMapDataType, cuuint32_t, void*, const cuuint64_t*,
    const cuuint64_t*, const cuuint32_t*, const cuuint32_t*,
    CUtensorMapInterleave, CUtensorMapSwizzle, CUtensorMapL2promotion,
    CUtensorMapFloatOOBfill);

extern "C" void kernel_launch(void* const* d_in, const int* in_sizes, int n_in,
                              void* d_out, int out_size) {
  const float* x = nullptr;
  const float* wgt = nullptr;
  const float* bias = nullptr;
  const int* bm = nullptr;
  for (int i = 0; i < n_in; i++) {
    long long sz = in_sizes[i];
    if (sz == (long long)MDIM * KDIM)       x    = (const float*)d_in[i];
    else if (sz == (long long)NDIM * KDIM)  wgt  = (const float*)d_in[i];
    else if (sz == NDIM)                    bias = (const float*)d_in[i];
    else if (sz == (NDIM / BLK) * (KDIM / BLK)) bm = (const int*)d_in[i];
  }

  void* wm_ptr = nullptr;
  void* xt_ptr = nullptr;
  void* lv_ptr = nullptr;
  cudaGetSymbolAddress(&wm_ptr, g_wm);
  cudaGetSymbolAddress(&xt_ptr, g_xt);
  cudaGetSymbolAddress(&lv_ptr, g_live);

  // 1) Pre-pass (one thread per 32-col k-block)
  premask_kernel<<<(NDIM * (KDIM / 32)) / 256, 256>>>(
      (const float4*)wgt, bm, (float*)wm_ptr);
  cvtx_kernel<<<(int)(((size_t)MDIM * (KDIM / 32)) / 256), 256>>>(
      (const float4*)x, (float*)xt_ptr);
  livemask_kernel<<<8, 256>>>(bm, (unsigned char*)lv_ptr);

  // 2) TMA descriptors
  EncodeTiledFn enc = nullptr;
  cudaDriverEntryPointQueryResult qr;
  cudaGetDriverEntryPoint("cuTensorMapEncodeTiled", (void**)&enc,
                          cudaEnableDefault, &qr);

  CUtensorMap tmA, tmB;
  {
    cuuint64_t dims[2]    = {(cuuint64_t)KDIM, (cuuint64_t)MDIM};
    cuuint64_t strides[1] = {(cuuint64_t)KDIM * sizeof(float)};
    cuuint32_t box[2]     = {KT, TM};
    cuuint32_t es[2]      = {1, 1};
    enc(&tmA, CU_TENSOR_MAP_DATA_TYPE_FLOAT32, 2, xt_ptr, dims, strides, box,
        es, CU_TENSOR_MAP_INTERLEAVE_NONE, CU_TENSOR_MAP_SWIZZLE_128B,
        CU_TENSOR_MAP_L2_PROMOTION_L2_128B, CU_TENSOR_MAP_FLOAT_OOB_FILL_NONE);
  }
  {
    cuuint64_t dims[2]    = {(cuuint64_t)KDIM, (cuuint64_t)NDIM};
    cuuint64_t strides[1] = {(cuuint64_t)KDIM * sizeof(float)};
    cuuint32_t box[2]     = {KT, 32};    // one 32x32 n-block per TMA
    cuuint32_t es[2]      = {1, 1};
    enc(&tmB, CU_TENSOR_MAP_DATA_TYPE_FLOAT32, 2, wm_ptr, dims, strides, box,
        es, CU_TENSOR_MAP_INTERLEAVE_NONE, CU_TENSOR_MAP_SWIZZLE_128B,
        CU_TENSOR_MAP_L2_PROMOTION_L2_128B, CU_TENSOR_MAP_FLOAT_OOB_FILL_NONE);
  }

  // 3) GEMM: grid.x = n-tiles (16), grid.y = m-tiles (64)
  cudaFuncSetAttribute(bsl_gemm_kernel,
                       cudaFuncAttributeMaxDynamicSharedMemorySize, SMEM_TOTAL);
  dim3 grid(NDIM / TN, MDIM / TM);
  bsl_gemm_kernel<<<grid, THREADS, SMEM_TOTAL>>>(tmA, tmB, bias, (float*)d_out);
}

// round 15
// speedup vs baseline: 1.4402x; 1.4402x over previous
#include <cuda_runtime.h>
#include <cuda.h>
#include <cstdint>
#include <cstddef>

// Problem dims
#define MDIM 8192
#define NDIM 4096
#define KDIM 4096
#define BLK  32

// GEMM tiling (R8 baseline — best known: 866.7us)
#define TM 128
#define TN 256
#define KT 32                 // fp32 elements per K-chunk = one K-block = 128B row
#define NSTAGES 4
#define NKITER (KDIM / KT)    // 128
#define NWC 16                // compute warps (2m x 8n, warp tile 64x32)
#define THREADS 544           // 16 compute warps + 1 producer warp

#define A_BYTES (TM * KT * 4)         // 16384
#define B_BYTES (TN * KT * 4)         // 32768
#define BBLK_BYTES (32 * KT * 4)      // 4096 per n-block
#define STAGE_BYTES (A_BYTES + B_BYTES)               // 49152
#define SMEM_DATA0 1024
#define SMEM_TOTAL (SMEM_DATA0 + NSTAGES * STAGE_BYTES)  // 197632

#define OFF_FULL(s)  (16 + (s) * 8)
#define OFF_EMPTY(s) (64 + (s) * 8)
#define OFF_LIVE     512              // 128 bytes: live mask per k-block

// Scratch (static device globals: allowed, no runtime alloc)
__device__ float g_wm[(size_t)NDIM * (size_t)KDIM];   // masked+tf32+permuted W
__device__ float g_xt[(size_t)MDIM * (size_t)KDIM];   // tf32+permuted x
__device__ unsigned char g_live[(NDIM / TN) * NKITER];  // [16][128]

// ---------------- device helpers ----------------

__device__ __forceinline__ uint32_t smem_u32(const void* p) {
  uint32_t r;
  asm("{ .reg .u64 t; cvta.to.shared.u64 t, %1; cvt.u32.u64 %0, t; }"
      : "=r"(r) : "l"(p));
  return r;
}
__device__ __forceinline__ void mbar_init(uint32_t a, uint32_t cnt) {
  asm volatile("mbarrier.init.shared::cta.b64 [%0], %1;"
               :: "r"(a), "r"(cnt) : "memory");
}
__device__ __forceinline__ void mbar_expect_tx(uint32_t a, uint32_t bytes) {
  asm volatile("mbarrier.arrive.expect_tx.shared::cta.b64 _, [%0], %1;"
               :: "r"(a), "r"(bytes) : "memory");
}
__device__ __forceinline__ void mbar_arrive(uint32_t a) {
  asm volatile("mbarrier.arrive.shared::cta.b64 _, [%0];"
               :: "r"(a) : "memory");
}
__device__ __forceinline__ void mbar_wait(uint32_t a, uint32_t parity) {
  asm volatile(
      "{\n\t.reg .pred P;\n\t"
      "WL%=:\n\t"
      "mbarrier.try_wait.parity.acquire.cta.shared::cta.b64 P, [%0], %1, 0x989680;\n\t"
      "@P bra WD%=;\n\t"
      "bra WL%=;\n\t"
      "WD%=:\n\t}"
      :: "r"(a), "r"(parity) : "memory");
}
__device__ __forceinline__ void tma_load_2d(uint32_t smem_dst, const void* map,
                                            int cx, int cy, uint32_t bar) {
  asm volatile(
      "cp.async.bulk.tensor.2d.shared::cta.global.tile.mbarrier::complete_tx::bytes "
      "[%0], [%1, {%2, %3}], [%4];"
      :: "r"(smem_dst), "l"(map), "r"(cx), "r"(cy), "r"(bar) : "memory");
}
__device__ __forceinline__ uint32_t f2tf32(float f) {
  uint32_t u;
  asm("cvt.rna.tf32.f32 %0, %1;" : "=r"(u) : "f"(f));
  return u;
}
__device__ __forceinline__ void lds64(uint32_t addr, uint32_t& x, uint32_t& y) {
  asm volatile("ld.shared.v2.u32 {%0, %1}, [%2];"
               : "=r"(x), "=r"(y) : "r"(addr));
}
__device__ __forceinline__ void mma_tf32(float* c, uint32_t a0, uint32_t a1,
                                         uint32_t a2, uint32_t a3,
                                         uint32_t b0, uint32_t b1) {
  asm volatile(
      "mma.sync.aligned.m16n8k8.row.col.f32.tf32.tf32.f32 "
      "{%0,%1,%2,%3}, {%4,%5,%6,%7}, {%8,%9}, {%0,%1,%2,%3};"
      : "+f"(c[0]), "+f"(c[1]), "+f"(c[2]), "+f"(c[3])
      : "r"(a0), "r"(a1), "r"(a2), "r"(a3), "r"(b0), "r"(b1));
}

// ---------------- column permutation (R4-verified, unchanged) ----------------
// off = (c4&1)*8 + ks*16 + (c4>>1)*64 + h*4 within each 128B k-block row.
// Conflict-free LDS.64 under the SW128 XOR (grp<<4).

__device__ __forceinline__ int perm_src_col(int p) {
  int h  = p & 1;
  int c4 = ((p >> 1) & 1) | (((p >> 4) & 1) << 1);
  int ks = (p >> 2) & 3;
  return ks * 8 + c4 + 4 * h;
}

// ---------------- pre-pass kernels ----------------

__global__ void __launch_bounds__(256)
premask_kernel(const float4* __restrict__ w, const int* __restrict__ bm,
               float* __restrict__ wm) {
  int t = blockIdx.x * 256 + threadIdx.x;     // [NDIM][KDIM/32]
  int o  = t >> 7;
  int kb = t & 127;
  if (bm[((o >> 5) << 7) + kb] == 0) return;  // dead blocks never TMA-loaded
  const float4* src = w + (size_t)t * 8;
  uint4* dst = reinterpret_cast<uint4*>(wm) + (size_t)t * 8;
  float v[32];
  #pragma unroll
  for (int q = 0; q < 8; q++) {
    float4 f = src[q];
    v[q * 4 + 0] = f.x; v[q * 4 + 1] = f.y; v[q * 4 + 2] = f.z; v[q * 4 + 3] = f.w;
  }
  uint32_t ov[32];
  #pragma unroll
  for (int p = 0; p < 32; p++) ov[p] = f2tf32(v[perm_src_col(p)]);
  #pragma unroll
  for (int q = 0; q < 8; q++)
    dst[q] = make_uint4(ov[q * 4], ov[q * 4 + 1], ov[q * 4 + 2], ov[q * 4 + 3]);
}

__global__ void __launch_bounds__(256)
cvtx_kernel(const float4* __restrict__ x, float* __restrict__ xt) {
  int t = blockIdx.x * 256 + threadIdx.x;
  const float4* src = x + (size_t)t * 8;
  uint4* dst = reinterpret_cast<uint4*>(xt) + (size_t)t * 8;
  float v[32];
  #pragma unroll
  for (int q = 0; q < 8; q++) {
    float4 f = src[q];
    v[q * 4 + 0] = f.x; v[q * 4 + 1] = f.y; v[q * 4 + 2] = f.z; v[q * 4 + 3] = f.w;
  }
  uint32_t ov[32];
  #pragma unroll
  for (int p = 0; p < 32; p++) ov[p] = f2tf32(v[perm_src_col(p)]);
  #pragma unroll
  for (int q = 0; q < 8; q++)
    dst[q] = make_uint4(ov[q * 4], ov[q * 4 + 1], ov[q * 4 + 2], ov[q * 4 + 3]);
}

__global__ void __launch_bounds__(256)
livemask_kernel(const int* __restrict__ bm, unsigned char* __restrict__ lv) {
  int t = blockIdx.x * 256 + threadIdx.x;   // 0..2047
  int cn = t >> 7, kb = t & 127;
  unsigned b = 0;
  #pragma unroll
  for (int j = 0; j < 8; j++)
    b |= (bm[(cn * 8 + j) * 128 + kb] ? 1u : 0u) << j;
  lv[t] = (unsigned char)b;
}

// ---------------- GEMM ----------------
// Exact R8 structure (best known). Two overhead cuts:
//  (1) each warp precomputes its 128-bit live vector via 4 ballots and
//      consumes it with m&1 / m>>=1 — no per-round lv LDS or shifts;
//  (2) ring loop unrolled 4x (q[4] x g[8] x st[4]): stage offsets, barrier
//      addresses and parity are compile-time per body; parity flips once per
//      ring pass. Geometry (j0=w>>1), k-order, parity discipline unchanged.

__device__ __forceinline__ void lds_frag_a(uint32_t Ab, uint32_t cx,
                                           uint32_t* a) {
  #pragma unroll
  for (int mt = 0; mt < 4; mt++) {
    lds64(Ab + mt * 2048 + cx,        a[mt * 4 + 0], a[mt * 4 + 2]);
    lds64(Ab + mt * 2048 + 1024 + cx, a[mt * 4 + 1], a[mt * 4 + 3]);
  }
}
__device__ __forceinline__ void lds_frag_b(uint32_t Bb, uint32_t cx,
                                           uint32_t* b) {
  #pragma unroll
  for (int nt = 0; nt < 4; nt++)
    lds64(Bb + nt * 1024 + cx, b[nt * 2], b[nt * 2 + 1]);
}

__device__ __forceinline__ void stage_mma(uint32_t Ab, uint32_t Bb,
                                          const uint32_t* cxs,
                                          float acc[4][4][4]) {
  uint32_t a[2][16], b[2][8];
  lds_frag_b(Bb, cxs[0], b[0]);
  lds_frag_a(Ab, cxs[0], a[0]);
  #pragma unroll
  for (int ks = 0; ks < 4; ks++) {
    const int cur = ks & 1, nxt = cur ^ 1;
    if (ks < 3) {
      lds_frag_b(Bb, cxs[ks + 1], b[nxt]);
      lds_frag_a(Ab, cxs[ks + 1], a[nxt]);
    }
    #pragma unroll
    for (int mt = 0; mt < 4; mt++)
      #pragma unroll
      for (int nt = 0; nt < 4; nt++)
        mma_tf32(acc[mt][nt], a[cur][mt * 4 + 0], a[cur][mt * 4 + 1],
                 a[cur][mt * 4 + 2], a[cur][mt * 4 + 3],
                 b[cur][nt * 2], b[cur][nt * 2 + 1]);
  }
}

__global__ void __launch_bounds__(THREADS, 1)
bsl_gemm_kernel(const __grid_constant__ CUtensorMap tmA,
                const __grid_constant__ CUtensorMap tmB,
                const float* __restrict__ bias,
                float* __restrict__ out) {
  extern __shared__ char smem[];
  const uint32_t sb = smem_u32(smem);
  const int tid  = threadIdx.x;
  const int w    = tid >> 5;
  const int lane = tid & 31;
  const int grp  = lane >> 2;
  const int c4   = lane & 3;

  // grid: x = n-tile (16), y = m-tile (64)  -> wave-blocked for L2 reuse
  const int n0 = blockIdx.x * TN;
  const int m0 = blockIdx.y * TM;

  if (tid == 0) {
    #pragma unroll
    for (int s = 0; s < NSTAGES; s++) {
      mbar_init(sb + OFF_FULL(s), 1);
      mbar_init(sb + OFF_EMPTY(s), NWC);
    }
    asm volatile("fence.proxy.async.shared::cta;" ::: "memory");
  }
  if (tid < 32) {
    reinterpret_cast<uint32_t*>(smem + OFF_LIVE)[tid] =
        reinterpret_cast<const uint32_t*>(g_live)[blockIdx.x * 32 + tid];
  }
  __syncthreads();

  const unsigned char* lv = reinterpret_cast<const unsigned char*>(smem + OFF_LIVE);

  if (w == NWC) {
    // -------- producer warp (identical to R8) --------
    if (lane == 0) {
      for (int kb = 0; kb < NKITER; kb++) {
        const int st = kb & (NSTAGES - 1);
        if (kb >= NSTAGES) mbar_wait(sb + OFF_EMPTY(st), ((kb - NSTAGES) >> 2) & 1);
        const unsigned L = lv[kb];
        const uint32_t tx = (L ? A_BYTES : 0u) + (uint32_t)__popc(L) * BBLK_BYTES;
        mbar_expect_tx(sb + OFF_FULL(st), tx);
        const uint32_t dst = sb + SMEM_DATA0 + st * STAGE_BYTES;
        if (L) tma_load_2d(dst, &tmA, kb * KT, m0, sb + OFF_FULL(st));
        #pragma unroll
        for (int j = 0; j < 8; j++)
          if ((L >> j) & 1)
            tma_load_2d(dst + A_BYTES + j * BBLK_BYTES, &tmB, kb * KT,
                        n0 + j * 32, sb + OFF_FULL(st));
      }
    }
    return;
  }

  // -------- compute warps: j0 = w>>1 (SMSP-balanced, R8), m-half = w&1 --
  const int j0  = w >> 1;            // the warp's n-block (0..7)
  const int wm_ = (w & 1) * 64;      // warp m offset (0 or 64)
  const int wn_ = j0 * 32;           // warp n offset

  // Ballot-precomputed per-warp live vector: lm[q] bit i = live(kb = q*32+i).
  uint32_t lm[4];
  #pragma unroll
  for (int q = 0; q < 4; q++) {
    unsigned bit = (lv[q * 32 + lane] >> j0) & 1u;
    lm[q] = __ballot_sync(0xffffffffu, bit);
  }

  const uint32_t arow0 = (uint32_t)((wm_ + grp) * 128);
  const uint32_t brow0 = (uint32_t)(j0 * BBLK_BYTES + grp * 128);
  const uint32_t xorb =
      (((uint32_t)(c4 & 1) << 3) | ((uint32_t)(c4 >> 1) << 6)) ^
      ((uint32_t)grp << 4);
  uint32_t cxs[4];
  #pragma unroll
  for (int ks = 0; ks < 4; ks++) cxs[ks] = ((uint32_t)(ks << 4)) ^ xorb;

  float acc[4][4][4];
  #pragma unroll
  for (int mt = 0; mt < 4; mt++)
    #pragma unroll
    for (int nt = 0; nt < 4; nt++)
      #pragma unroll
      for (int r = 0; r < 4; r++) acc[mt][nt][r] = 0.f;

  // Ring loop: 4 q-chunks x 8 ring passes x 4 stages = 128 rounds.
  // Parity flips once per ring pass ((kb>>2)&1 pattern preserved).
  int ph = 0;
  #pragma unroll 1
  for (int q = 0; q < 4; q++) {
    uint32_t m = lm[q];
    #pragma unroll 1
    for (int g = 0; g < 8; g++) {
      #pragma unroll
      for (int st = 0; st < NSTAGES; st++) {
        mbar_wait(sb + OFF_FULL(st), ph);
        if (m & 1u) {
          const uint32_t base = sb + (SMEM_DATA0 + st * STAGE_BYTES);
          stage_mma(base + arow0, base + A_BYTES + brow0, cxs, acc);
        }
        m >>= 1;
        if (lane == 0) mbar_arrive(sb + OFF_EMPTY(st));
      }
      ph ^= 1;
    }
  }

  // -------- epilogue --------
  #pragma unroll
  for (int nt = 0; nt < 4; nt++) {
    const int col = n0 + wn_ + nt * 8 + c4 * 2;
    const float2 bv = *reinterpret_cast<const float2*>(bias + col);
    #pragma unroll
    for (int mt = 0; mt < 4; mt++) {
      const int row = m0 + wm_ + mt * 16 + grp;
      float2 o0, o1;
      o0.x = acc[mt][nt][0] + bv.x;
      o0.y = acc[mt][nt][1] + bv.y;
      o1.x = acc[mt][nt][2] + bv.x;
      o1.y = acc[mt][nt][3] + bv.y;
      *reinterpret_cast<float2*>(out + (size_t)row * NDIM + col) = o0;
      *reinterpret_cast<float2*>(out + (size_t)(row + 8) * NDIM + col) = o1;
    }
  }
}

// ---------------- host launch ----------------

typedef CUresult (*EncodeTiledFn)(
    CUtensorMap*, CUtensorMapDataType, cuuint32_t, void*, const cuuint64_t*,
    const cuuint64_t*, const cuuint32_t*, const cuuint32_t*,
    CUtensorMapInterleave, CUtensorMapSwizzle, CUtensorMapL2promotion,
    CUtensorMapFloatOOBfill);

extern "C" void kernel_launch(void* const* d_in, const int* in_sizes, int n_in,
                              void* d_out, int out_size) {
  const float* x = nullptr;
  const float* wgt = nullptr;
  const float* bias = nullptr;
  const int* bm = nullptr;
  for (int i = 0; i < n_in; i++) {
    long long sz = in_sizes[i];
    if (sz == (long long)MDIM * KDIM)       x    = (const float*)d_in[i];
    else if (sz == (long long)NDIM * KDIM)  wgt  = (const float*)d_in[i];
    else if (sz == NDIM)                    bias = (const float*)d_in[i];
    else if (sz == (NDIM / BLK) * (KDIM / BLK)) bm = (const int*)d_in[i];
  }

  void* wm_ptr = nullptr;
  void* xt_ptr = nullptr;
  void* lv_ptr = nullptr;
  cudaGetSymbolAddress(&wm_ptr, g_wm);
  cudaGetSymbolAddress(&xt_ptr, g_xt);
  cudaGetSymbolAddress(&lv_ptr, g_live);

  // 1) Pre-pass (one thread per 32-col k-block)
  premask_kernel<<<(NDIM * (KDIM / 32)) / 256, 256>>>(
      (const float4*)wgt, bm, (float*)wm_ptr);
  cvtx_kernel<<<(int)(((size_t)MDIM * (KDIM / 32)) / 256), 256>>>(
      (const float4*)x, (float*)xt_ptr);
  livemask_kernel<<<8, 256>>>(bm, (unsigned char*)lv_ptr);

  // 2) TMA descriptors
  EncodeTiledFn enc = nullptr;
  cudaDriverEntryPointQueryResult qr;
  cudaGetDriverEntryPoint("cuTensorMapEncodeTiled", (void**)&enc,
                          cudaEnableDefault, &qr);

  CUtensorMap tmA, tmB;
  {
    cuuint64_t dims[2]    = {(cuuint64_t)KDIM, (cuuint64_t)MDIM};
    cuuint64_t strides[1] = {(cuuint64_t)KDIM * sizeof(float)};
    cuuint32_t box[2]     = {KT, TM};
    cuuint32_t es[2]      = {1, 1};
    enc(&tmA, CU_TENSOR_MAP_DATA_TYPE_FLOAT32, 2, xt_ptr, dims, strides, box,
        es, CU_TENSOR_MAP_INTERLEAVE_NONE, CU_TENSOR_MAP_SWIZZLE_128B,
        CU_TENSOR_MAP_L2_PROMOTION_L2_128B, CU_TENSOR_MAP_FLOAT_OOB_FILL_NONE);
  }
  {
    cuuint64_t dims[2]    = {(cuuint64_t)KDIM, (cuuint64_t)NDIM};
    cuuint64_t strides[1] = {(cuuint64_t)KDIM * sizeof(float)};
    cuuint32_t box[2]     = {KT, 32};    // one 32x32 n-block per TMA
    cuuint32_t es[2]      = {1, 1};
    enc(&tmB, CU_TENSOR_MAP_DATA_TYPE_FLOAT32, 2, wm_ptr, dims, strides, box,
        es, CU_TENSOR_MAP_INTERLEAVE_NONE, CU_TENSOR_MAP_SWIZZLE_128B,
        CU_TENSOR_MAP_L2_PROMOTION_L2_128B, CU_TENSOR_MAP_FLOAT_OOB_FILL_NONE);
  }

  // 3) GEMM: grid.x = n-tiles (16), grid.y = m-tiles (64)
  cudaFuncSetAttribute(bsl_gemm_kernel,
                       cudaFuncAttributeMaxDynamicSharedMemorySize, SMEM_TOTAL);
  dim3 grid(NDIM / TN, MDIM / TM);
  bsl_gemm_kernel<<<grid, THREADS, SMEM_TOTAL>>>(tmA, tmB, bias, (float*)d_out);
}

// round 16
// speedup vs baseline: 1.6483x; 1.1445x over previous
#include <cuda_runtime.h>
#include <cuda.h>
#include <cstdint>
#include <cstddef>

// Problem dims
#define MDIM 8192
#define NDIM 4096
#define KDIM 4096
#define BLK  32

// GEMM tiling (R15 baseline — best known: 787.2us)
#define TM 128
#define TN 256
#define KT 32                 // fp32 elements per K-chunk = one K-block = 128B row
#define NSTAGES 4
#define NKITER (KDIM / KT)    // 128
#define NWC 16                // compute warps (2m x 8n, warp tile 64x32)
#define THREADS 544           // 16 compute warps + 1 producer warp

#define A_BYTES (TM * KT * 4)         // 16384
#define B_BYTES (TN * KT * 4)         // 32768
#define BBLK_BYTES (32 * KT * 4)      // 4096 per n-block
#define STAGE_BYTES (A_BYTES + B_BYTES)               // 49152
#define SMEM_DATA0 1024
#define SMEM_TOTAL (SMEM_DATA0 + NSTAGES * STAGE_BYTES)  // 197632

#define OFF_FULL(s)  (16 + (s) * 8)
#define OFF_EMPTY(s) (64 + (s) * 8)
#define OFF_LIVE     512              // 128 bytes: live mask per k-block

// Scratch (static device globals: allowed, no runtime alloc).
// NOTE: no g_xt anymore — A is TMA'd straight from the input x (raw fp32).
// The tf32 HMMA truncates the low mantissa bits of A (RZ); the resulting
// -2^-11 multiplicative bias is cancelled by scaling W with (1+2^-11) in
// premask. W itself is RNA-rounded so its truncation is a no-op.
__device__ float g_wm[(size_t)NDIM * (size_t)KDIM];   // masked+tf32+permuted W
__device__ unsigned char g_live[(NDIM / TN) * NKITER];  // [16][128]

// ---------------- device helpers ----------------

__device__ __forceinline__ uint32_t smem_u32(const void* p) {
  uint32_t r;
  asm("{ .reg .u64 t; cvta.to.shared.u64 t, %1; cvt.u32.u64 %0, t; }"
      : "=r"(r) : "l"(p));
  return r;
}
__device__ __forceinline__ void mbar_init(uint32_t a, uint32_t cnt) {
  asm volatile("mbarrier.init.shared::cta.b64 [%0], %1;"
               :: "r"(a), "r"(cnt) : "memory");
}
__device__ __forceinline__ void mbar_expect_tx(uint32_t a, uint32_t bytes) {
  asm volatile("mbarrier.arrive.expect_tx.shared::cta.b64 _, [%0], %1;"
               :: "r"(a), "r"(bytes) : "memory");
}
__device__ __forceinline__ void mbar_arrive(uint32_t a) {
  asm volatile("mbarrier.arrive.shared::cta.b64 _, [%0];"
               :: "r"(a) : "memory");
}
__device__ __forceinline__ void mbar_wait(uint32_t a, uint32_t parity) {
  asm volatile(
      "{\n\t.reg .pred P;\n\t"
      "WL%=:\n\t"
      "mbarrier.try_wait.parity.acquire.cta.shared::cta.b64 P, [%0], %1, 0x989680;\n\t"
      "@P bra WD%=;\n\t"
      "bra WL%=;\n\t"
      "WD%=:\n\t}"
      :: "r"(a), "r"(parity) : "memory");
}
__device__ __forceinline__ void tma_load_2d(uint32_t smem_dst, const void* map,
                                            int cx, int cy, uint32_t bar) {
  asm volatile(
      "cp.async.bulk.tensor.2d.shared::cta.global.tile.mbarrier::complete_tx::bytes "
      "[%0], [%1, {%2, %3}], [%4];"
      :: "r"(smem_dst), "l"(map), "r"(cx), "r"(cy), "r"(bar) : "memory");
}
__device__ __forceinline__ uint32_t f2tf32(float f) {
  uint32_t u;
  asm("cvt.rna.tf32.f32 %0, %1;" : "=r"(u) : "f"(f));
  return u;
}
__device__ __forceinline__ void lds64(uint32_t addr, uint32_t& x, uint32_t& y) {
  asm volatile("ld.shared.v2.u32 {%0, %1}, [%2];"
               : "=r"(x), "=r"(y) : "r"(addr));
}
__device__ __forceinline__ uint32_t lds32(uint32_t addr) {
  uint32_t x;
  asm volatile("ld.shared.u32 %0, [%1];" : "=r"(x) : "r"(addr));
  return x;
}
__device__ __forceinline__ void mma_tf32(float* c, uint32_t a0, uint32_t a1,
                                         uint32_t a2, uint32_t a3,
                                         uint32_t b0, uint32_t b1) {
  asm volatile(
      "mma.sync.aligned.m16n8k8.row.col.f32.tf32.tf32.f32 "
      "{%0,%1,%2,%3}, {%4,%5,%6,%7}, {%8,%9}, {%0,%1,%2,%3};"
      : "+f"(c[0]), "+f"(c[1]), "+f"(c[2]), "+f"(c[3])
      : "r"(a0), "r"(a1), "r"(a2), "r"(a3), "r"(b0), "r"(b1));
}

// ---------------- column permutation (W/B only, R4-verified) ----------------
// off = (c4&1)*8 + ks*16 + (c4>>1)*64 + h*4 within each 128B k-block row ->
// conflict-free LDS.64 under the SW128 XOR (grp<<4).
// A (x) is now UNPERMUTED: fragment col ks*8+c4(+4) lives at byte
// c4*4 + (((2ks+h)^grp)<<4) after swizzle — bits {2,3} vs {4,5,6} are
// disjoint, so 32 lanes hit 32 distinct words: conflict-free LDS.32.

__device__ __forceinline__ int perm_src_col(int p) {
  int h  = p & 1;
  int c4 = ((p >> 1) & 1) | (((p >> 4) & 1) << 1);
  int ks = (p >> 2) & 3;
  return ks * 8 + c4 + 4 * h;
}

// ---------------- pre-pass kernels ----------------

// W: mask + bias-compensation scale (1+2^-11) + tf32-round + permute.
__global__ void __launch_bounds__(256)
premask_kernel(const float4* __restrict__ w, const int* __restrict__ bm,
               float* __restrict__ wm) {
  int t = blockIdx.x * 256 + threadIdx.x;     // [NDIM][KDIM/32]
  int o  = t >> 7;
  int kb = t & 127;
  if (bm[((o >> 5) << 7) + kb] == 0) return;  // dead blocks never TMA-loaded
  const float comp = 1.00048828125f;          // 1 + 2^-11: cancels A-truncation bias
  const float4* src = w + (size_t)t * 8;
  uint4* dst = reinterpret_cast<uint4*>(wm) + (size_t)t * 8;
  float v[32];
  #pragma unroll
  for (int q = 0; q < 8; q++) {
    float4 f = src[q];
    v[q * 4 + 0] = f.x * comp; v[q * 4 + 1] = f.y * comp;
    v[q * 4 + 2] = f.z * comp; v[q * 4 + 3] = f.w * comp;
  }
  uint32_t ov[32];
  #pragma unroll
  for (int p = 0; p < 32; p++) ov[p] = f2tf32(v[perm_src_col(p)]);
  #pragma unroll
  for (int q = 0; q < 8; q++)
    dst[q] = make_uint4(ov[q * 4], ov[q * 4 + 1], ov[q * 4 + 2], ov[q * 4 + 3]);
}

__global__ void __launch_bounds__(256)
livemask_kernel(const int* __restrict__ bm, unsigned char* __restrict__ lv) {
  int t = blockIdx.x * 256 + threadIdx.x;   // 0..2047
  int cn = t >> 7, kb = t & 127;
  unsigned b = 0;
  #pragma unroll
  for (int j = 0; j < 8; j++)
    b |= (bm[(cn * 8 + j) * 128 + kb] ? 1u : 0u) << j;
  lv[t] = (unsigned char)b;
}

// ---------------- GEMM ----------------
// R15 structure (ballot masks + 4x-unrolled ring). A fragments now come from
// unpermuted raw-fp32 x via conflict-free LDS.32 (same wavefront count as the
// old LDS.64 path, +8 issue slots/ks at 36% issue util — negligible).

__device__ __forceinline__ void lds_frag_a(uint32_t Ab, uint32_t cx0,
                                           uint32_t cx1, uint32_t* a) {
  #pragma unroll
  for (int mt = 0; mt < 4; mt++) {
    a[mt * 4 + 0] = lds32(Ab + mt * 2048 + cx0);
    a[mt * 4 + 2] = lds32(Ab + mt * 2048 + cx1);
    a[mt * 4 + 1] = lds32(Ab + mt * 2048 + 1024 + cx0);
    a[mt * 4 + 3] = lds32(Ab + mt * 2048 + 1024 + cx1);
  }
}
__device__ __forceinline__ void lds_frag_b(uint32_t Bb, uint32_t cx,
                                           uint32_t* b) {
  #pragma unroll
  for (int nt = 0; nt < 4; nt++)
    lds64(Bb + nt * 1024 + cx, b[nt * 2], b[nt * 2 + 1]);
}

__device__ __forceinline__ void stage_mma(uint32_t Ab, uint32_t Bb,
                                          const uint32_t* cxA,  // [8]
                                          const uint32_t* cxB,  // [4]
                                          float acc[4][4][4]) {
  uint32_t a[2][16], b[2][8];
  lds_frag_b(Bb, cxB[0], b[0]);
  lds_frag_a(Ab, cxA[0], cxA[1], a[0]);
  #pragma unroll
  for (int ks = 0; ks < 4; ks++) {
    const int cur = ks & 1, nxt = cur ^ 1;
    if (ks < 3) {
      lds_frag_b(Bb, cxB[ks + 1], b[nxt]);
      lds_frag_a(Ab, cxA[2 * ks + 2], cxA[2 * ks + 3], a[nxt]);
    }
    #pragma unroll
    for (int mt = 0; mt < 4; mt++)
      #pragma unroll
      for (int nt = 0; nt < 4; nt++)
        mma_tf32(acc[mt][nt], a[cur][mt * 4 + 0], a[cur][mt * 4 + 1],
                 a[cur][mt * 4 + 2], a[cur][mt * 4 + 3],
                 b[cur][nt * 2], b[cur][nt * 2 + 1]);
  }
}

__global__ void __launch_bounds__(THREADS, 1)
bsl_gemm_kernel(const __grid_constant__ CUtensorMap tmA,
                const __grid_constant__ CUtensorMap tmB,
                const float* __restrict__ bias,
                float* __restrict__ out) {
  extern __shared__ char smem[];
  const uint32_t sb = smem_u32(smem);
  const int tid  = threadIdx.x;
  const int w    = tid >> 5;
  const int lane = tid & 31;
  const int grp  = lane >> 2;
  const int c4   = lane & 3;

  // grid: x = n-tile (16), y = m-tile (64)  -> wave-blocked for L2 reuse
  const int n0 = blockIdx.x * TN;
  const int m0 = blockIdx.y * TM;

  if (tid == 0) {
    #pragma unroll
    for (int s = 0; s < NSTAGES; s++) {
      mbar_init(sb + OFF_FULL(s), 1);
      mbar_init(sb + OFF_EMPTY(s), NWC);
    }
    asm volatile("fence.proxy.async.shared::cta;" ::: "memory");
  }
  if (tid < 32) {
    reinterpret_cast<uint32_t*>(smem + OFF_LIVE)[tid] =
        reinterpret_cast<const uint32_t*>(g_live)[blockIdx.x * 32 + tid];
  }
  __syncthreads();

  const unsigned char* lv = reinterpret_cast<const unsigned char*>(smem + OFF_LIVE);

  if (w == NWC) {
    // -------- producer warp (identical to R8/R15) --------
    if (lane == 0) {
      for (int kb = 0; kb < NKITER; kb++) {
        const int st = kb & (NSTAGES - 1);
        if (kb >= NSTAGES) mbar_wait(sb + OFF_EMPTY(st), ((kb - NSTAGES) >> 2) & 1);
        const unsigned L = lv[kb];
        const uint32_t tx = (L ? A_BYTES : 0u) + (uint32_t)__popc(L) * BBLK_BYTES;
        mbar_expect_tx(sb + OFF_FULL(st), tx);
        const uint32_t dst = sb + SMEM_DATA0 + st * STAGE_BYTES;
        if (L) tma_load_2d(dst, &tmA, kb * KT, m0, sb + OFF_FULL(st));
        #pragma unroll
        for (int j = 0; j < 8; j++)
          if ((L >> j) & 1)
            tma_load_2d(dst + A_BYTES + j * BBLK_BYTES, &tmB, kb * KT,
                        n0 + j * 32, sb + OFF_FULL(st));
      }
    }
    return;
  }

  // -------- compute warps: j0 = w>>1 (SMSP-balanced), m-half = w&1 --
  const int j0  = w >> 1;            // the warp's n-block (0..7)
  const int wm_ = (w & 1) * 64;      // warp m offset (0 or 64)
  const int wn_ = j0 * 32;           // warp n offset

  // Ballot-precomputed per-warp live vector: lm[q] bit i = live(kb = q*32+i).
  uint32_t lm[4];
  #pragma unroll
  for (int q = 0; q < 4; q++) {
    unsigned bit = (lv[q * 32 + lane] >> j0) & 1u;
    lm[q] = __ballot_sync(0xffffffffu, bit);
  }

  const uint32_t arow0 = (uint32_t)((wm_ + grp) * 128);
  const uint32_t brow0 = (uint32_t)(j0 * BBLK_BYTES + grp * 128);
  // B (permuted): c4 -> bits {3,6}; ks bits {4,5}; XOR grp<<4.
  const uint32_t xorbB =
      (((uint32_t)(c4 & 1) << 3) | ((uint32_t)(c4 >> 1) << 6)) ^
      ((uint32_t)grp << 4);
  uint32_t cxB[4];
  #pragma unroll
  for (int ks = 0; ks < 4; ks++) cxB[ks] = ((uint32_t)(ks << 4)) ^ xorbB;
  // A (unpermuted): byte = c4*4 + (((2ks+h)^grp)<<4).
  uint32_t cxA[8];
  #pragma unroll
  for (int ks = 0; ks < 4; ks++)
    #pragma unroll
    for (int h = 0; h < 2; h++)
      cxA[2 * ks + h] =
          ((uint32_t)(c4 << 2)) + ((uint32_t)(((2 * ks + h) ^ grp)) << 4);

  float acc[4][4][4];
  #pragma unroll
  for (int mt = 0; mt < 4; mt++)
    #pragma unroll
    for (int nt = 0; nt < 4; nt++)
      #pragma unroll
      for (int r = 0; r < 4; r++) acc[mt][nt][r] = 0.f;

  // Ring loop: 4 q-chunks x 8 ring passes x 4 stages = 128 rounds.
  int ph = 0;
  #pragma unroll 1
  for (int q = 0; q < 4; q++) {
    uint32_t m = lm[q];
    #pragma unroll 1
    for (int g = 0; g < 8; g++) {
      #pragma unroll
      for (int st = 0; st < NSTAGES; st++) {
        mbar_wait(sb + OFF_FULL(st), ph);
        if (m & 1u) {
          const uint32_t base = sb + (SMEM_DATA0 + st * STAGE_BYTES);
          stage_mma(base + arow0, base + A_BYTES + brow0, cxA, cxB, acc);
        }
        m >>= 1;
        if (lane == 0) mbar_arrive(sb + OFF_EMPTY(st));
      }
      ph ^= 1;
    }
  }

  // -------- epilogue --------
  #pragma unroll
  for (int nt = 0; nt < 4; nt++) {
    const int col = n0 + wn_ + nt * 8 + c4 * 2;
    const float2 bv = *reinterpret_cast<const float2*>(bias + col);
    #pragma unroll
    for (int mt = 0; mt < 4; mt++) {
      const int row = m0 + wm_ + mt * 16 + grp;
      float2 o0, o1;
      o0.x = acc[mt][nt][0] + bv.x;
      o0.y = acc[mt][nt][1] + bv.y;
      o1.x = acc[mt][nt][2] + bv.x;
      o1.y = acc[mt][nt][3] + bv.y;
      *reinterpret_cast<float2*>(out + (size_t)row * NDIM + col) = o0;
      *reinterpret_cast<float2*>(out + (size_t)(row + 8) * NDIM + col) = o1;
    }
  }
}

// ---------------- host launch ----------------

typedef CUresult (*EncodeTiledFn)(
    CUtensorMap*, CUtensorMapDataType, cuuint32_t, void*, const cuuint64_t*,
    const cuuint64_t*, const cuuint32_t*, const cuuint32_t*,
    CUtensorMapInterleave, CUtensorMapSwizzle, CUtensorMapL2promotion,
    CUtensorMapFloatOOBfill);

extern "C" void kernel_launch(void* const* d_in, const int* in_sizes, int n_in,
                              void* d_out, int out_size) {
  const float* x = nullptr;
  const float* wgt = nullptr;
  const float* bias = nullptr;
  const int* bm = nullptr;
  for (int i = 0; i < n_in; i++) {
    long long sz = in_sizes[i];
    if (sz == (long long)MDIM * KDIM)       x    = (const float*)d_in[i];
    else if (sz == (long long)NDIM * KDIM)  wgt  = (const float*)d_in[i];
    else if (sz == NDIM)                    bias = (const float*)d_in[i];
    else if (sz == (NDIM / BLK) * (KDIM / BLK)) bm = (const int*)d_in[i];
  }

  void* wm_ptr = nullptr;
  void* lv_ptr = nullptr;
  cudaGetSymbolAddress(&wm_ptr, g_wm);
  cudaGetSymbolAddress(&lv_ptr, g_live);

  // 1) Pre-pass (no cvtx anymore — A is TMA'd directly from x)
  premask_kernel<<<(NDIM * (KDIM / 32)) / 256, 256>>>(
      (const float4*)wgt, bm, (float*)wm_ptr);
  livemask_kernel<<<8, 256>>>(bm, (unsigned char*)lv_ptr);

  // 2) TMA descriptors
  EncodeTiledFn enc = nullptr;
  cudaDriverEntryPointQueryResult qr;
  cudaGetDriverEntryPoint("cuTensorMapEncodeTiled", (void**)&enc,
                          cudaEnableDefault, &qr);

  CUtensorMap tmA, tmB;
  {
    cuuint64_t dims[2]    = {(cuuint64_t)KDIM, (cuuint64_t)MDIM};
    cuuint64_t strides[1] = {(cuuint64_t)KDIM * sizeof(float)};
    cuuint32_t box[2]     = {KT, TM};
    cuuint32_t es[2]      = {1, 1};
    enc(&tmA, CU_TENSOR_MAP_DATA_TYPE_FLOAT32, 2, (void*)x, dims, strides, box,
        es, CU_TENSOR_MAP_INTERLEAVE_NONE, CU_TENSOR_MAP_SWIZZLE_128B,
        CU_TENSOR_MAP_L2_PROMOTION_L2_128B, CU_TENSOR_MAP_FLOAT_OOB_FILL_NONE);
  }
  {
    cuuint64_t dims[2]    = {(cuuint64_t)KDIM, (cuuint64_t)NDIM};
    cuuint64_t strides[1] = {(cuuint64_t)KDIM * sizeof(float)};
    cuuint32_t box[2]     = {KT, 32};    // one 32x32 n-block per TMA
    cuuint32_t es[2]      = {1, 1};
    enc(&tmB, CU_TENSOR_MAP_DATA_TYPE_FLOAT32, 2, wm_ptr, dims, strides, box,
        es, CU_TENSOR_MAP_INTERLEAVE_NONE, CU_TENSOR_MAP_SWIZZLE_128B,
        CU_TENSOR_MAP_L2_PROMOTION_L2_128B, CU_TENSOR_MAP_FLOAT_OOB_FILL_NONE);
  }

  // 3) GEMM: grid.x = n-tiles (16), grid.y = m-tiles (64)
  cudaFuncSetAttribute(bsl_gemm_kernel,
                       cudaFuncAttributeMaxDynamicSharedMemorySize, SMEM_TOTAL);
  dim3 grid(NDIM / TN, MDIM / TM);
  bsl_gemm_kernel<<<grid, THREADS, SMEM_TOTAL>>>(tmA, tmB, bias, (float*)d_out);
}